// round 6
// baseline (speedup 1.0000x reference)
#include <cuda_runtime.h>

#define TT 128
#define BB 512
#define QQ 50
#define BQ (BB * QQ)                 // 25600
#define GAMMA_F 0.99f
#define NCH 8
#define CHL 16
#define TILE 32                      // t-rows per fused block
#define RST 52                       // smem row stride, 16B aligned
#define NTHR 128

// Per-chunk affine composites per chain: rets[chunk_lo] = A*rets[chunk_hi+1] + B
__device__ float2 g_AB[NCH * BQ];

// ---------------------------------------------------------------------------
// Kernel 1: chunk composites. Thread = 2 q-adjacent chains (same b), with the
// 16-step chunk split into two independent 8-step halves for 2x MLP.
// ---------------------------------------------------------------------------
__global__ __launch_bounds__(128)
void k_scan(const float* __restrict__ reward,
            const int*   __restrict__ step_type,
            const float* __restrict__ discount,
            const float* __restrict__ tvalue,
            float*       __restrict__ out)
{
    const int p = blockIdx.x * 128 + threadIdx.x;   // 0..12799 chain-pair
    const int c = blockIdx.y;
    if (c == 0 && p < BB) out[(TT - 1) * BB + p] = 0.0f;   // poisoned last row
    const int n = 2 * p;
    const int b = n / QQ;
    const int lo = c * CHL;
    const int hi = (c == NCH - 1) ? (TT - 2) : (lo + CHL - 1);

    // upper half: t = hi .. lo+8 (7 or 8 steps); lower half: t = lo+7 .. lo
    float Au = 1.0f, Bu0 = 0.0f, Bu1 = 0.0f;
    float Al = 1.0f, Bl0 = 0.0f, Bl1 = 0.0f;
    #pragma unroll
    for (int k = 0; k < 8; ++k) {
        const int tu = hi - k;
        const int tl = lo + 7 - k;
        if (tu >= lo + 8) {
            float2 tv = *(const float2*)&tvalue[tu * BQ + n];
            int   il = step_type[tu * BB + b];
            float r  = reward[(tu + 1) * BB + b];
            float d  = discount[(tu + 1) * BB + b] * GAMMA_F;
            float a  = (il == 2) ? 0.0f : d;
            Au  = a * Au;
            Bu0 = fmaf(a, Bu0, (il == 2) ? tv.x : r);
            Bu1 = fmaf(a, Bu1, (il == 2) ? tv.y : r);
        }
        {
            float2 tv = *(const float2*)&tvalue[tl * BQ + n];
            int   il = step_type[tl * BB + b];
            float r  = reward[(tl + 1) * BB + b];
            float d  = discount[(tl + 1) * BB + b] * GAMMA_F;
            float a  = (il == 2) ? 0.0f : d;
            Al  = a * Al;
            Bl0 = fmaf(a, Bl0, (il == 2) ? tv.x : r);
            Bl1 = fmaf(a, Bl1, (il == 2) ? tv.y : r);
        }
    }
    // rets[lo] = Al*(Au*x + Bu) + Bl  ->  A = Al*Au, B = Al*Bu + Bl
    g_AB[c * BQ + n]     = make_float2(Al * Au, fmaf(Al, Bu0, Bl0));
    g_AB[c * BQ + n + 1] = make_float2(Al * Au, fmaf(Al, Bu1, Bl1));
}

// ---------------------------------------------------------------------------
// Kernel 2 (fused): per (b, 32-t tile): seed-compose, in-smem walk, pairwise
// quantile-Huber. 128 threads, 14 blocks/SM -> 2072 slots >= 2048 blocks.
// ---------------------------------------------------------------------------

#define PAIR2(r2_, nv2_, S2_, D2_) do {                                        \
    unsigned long long x2_, c2_, m2_, t2_;                                     \
    asm("add.rn.f32x2 %0, %1, %2;" : "=l"(x2_) : "l"(r2_), "l"(nv2_));         \
    float xl_, xh_;                                                            \
    asm("mov.b64 {%0, %1}, %2;" : "=f"(xl_), "=f"(xh_) : "l"(x2_));            \
    float ml_ = fminf(fabsf(xl_), 1.0f);                                       \
    float mh_ = fminf(fabsf(xh_), 1.0f);                                       \
    float cl_ = __int_as_float((__float_as_int(xl_) & 0x80000000) |            \
                               __float_as_int(ml_));                           \
    float ch_ = __int_as_float((__float_as_int(xh_) & 0x80000000) |            \
                               __float_as_int(mh_));                           \
    asm("mov.b64 %0, {%1, %2};" : "=l"(c2_) : "f"(cl_), "f"(ch_));             \
    asm("mov.b64 %0, {%1, %2};" : "=l"(m2_) : "f"(ml_), "f"(mh_));             \
    asm("fma.rn.f32x2 %0, %1, %2, %3;" : "=l"(t2_)                             \
        : "l"(c2_), "l"(MH2), "l"(x2_));                                       \
    asm("fma.rn.f32x2 %0, %1, %2, %0;" : "+l"(S2_) : "l"(c2_), "l"(t2_));      \
    asm("fma.rn.f32x2 %0, %1, %2, %0;" : "+l"(D2_) : "l"(m2_), "l"(t2_));      \
} while (0)

__global__ __launch_bounds__(NTHR, 14)
void k_fused(const float* __restrict__ reward,
             const int*   __restrict__ step_type,
             const float* __restrict__ discount,
             const float* __restrict__ value,
             const float* __restrict__ tvalue,
             float*       __restrict__ out)
{
    __shared__ __align__(16) float s_ret[TILE][RST];
    __shared__ float s_part[TILE][QQ];
    __shared__ float s_a[TILE], s_r[TILE];
    __shared__ int   s_il[TILE];

    const int tid = threadIdx.x;
    const int b   = blockIdx.x;
    const int c0  = blockIdx.y;                      // tile 0..3
    const int lo  = c0 * TILE;
    const int hi  = (c0 == 3) ? (TT - 2) : (lo + TILE - 1);
    const int nu  = hi - lo + 1;                     // 32 or 31

    // ---- Stage tvalue rows (float2) + per-t scalars ----
    const int nstage = nu * (QQ / 2);
    for (int idx = tid; idx < nstage; idx += NTHR) {
        const int u  = idx / (QQ / 2);
        const int q2 = idx - u * (QQ / 2);
        ((float2*)&s_ret[u][0])[q2] =
            *(const float2*)&tvalue[(lo + u) * BQ + b * QQ + 2 * q2];
    }
    if (tid < nu) {
        const int t = lo + tid;
        const int il = step_type[t * BB + b];
        s_il[tid] = il;
        s_r[tid]  = reward[(t + 1) * BB + b];
        s_a[tid]  = (il == 2) ? 0.0f
                              : discount[(t + 1) * BB + b] * GAMMA_F;
    }

    // ---- Seed compose (independent of staging; overlaps it) ----
    float carry = 0.0f;
    if (tid < QQ) {
        carry = tvalue[(TT - 1) * BQ + b * QQ + tid];        // rets[127]
        for (int cc = NCH - 1; cc >= 2 * c0 + 2; --cc) {
            float2 ab = g_AB[cc * BQ + b * QQ + tid];
            carry = fmaf(ab.x, carry, ab.y);
        }
    }
    __syncthreads();

    // ---- In-smem walk: rets for this tile ----
    if (tid < QQ) {
        for (int k = nu - 1; k >= 0; --k) {
            float tv = s_ret[k][tid];
            float bb = (s_il[k] == 2) ? tv : s_r[k];
            carry = fmaf(s_a[k], carry, bb);
            s_ret[k][tid] = carry;
        }
    }
    __syncthreads();

    // ---- Pairwise quantile-Huber: item = (u, j-pair) ----
    const int nitems = nu * 25;
    for (int it = tid; it < nitems; it += NTHR) {
        const int u  = it / 25;
        const int jp = it - u * 25;

        const float2 v2 = *(const float2*)&value[(lo + u) * BQ + b * QQ + 2 * jp];
        unsigned long long nv2a, nv2b;
        {
            float na = -v2.x, nb = -v2.y;
            asm("mov.b64 %0, {%1, %1};" : "=l"(nv2a) : "f"(na));
            asm("mov.b64 %0, {%1, %1};" : "=l"(nv2b) : "f"(nb));
        }
        const unsigned long long MH2 = 0xBF000000BF000000ULL;   // (-0.5,-0.5)
        unsigned long long S2a = 0, D2a = 0, S2b = 0, D2b = 0;

        const ulonglong2* rp2 = (const ulonglong2*)&s_ret[u][0];
        #pragma unroll
        for (int p = 0; p < 12; ++p) {               // 48 returns via LDS.128
            ulonglong2 rr = rp2[p];
            PAIR2(rr.x, nv2a, S2a, D2a);
            PAIR2(rr.x, nv2b, S2b, D2b);
            PAIR2(rr.y, nv2a, S2a, D2a);
            PAIR2(rr.y, nv2b, S2b, D2b);
        }
        {                                            // returns 48, 49
            unsigned long long rt_ = *(const unsigned long long*)&s_ret[u][48];
            PAIR2(rt_, nv2a, S2a, D2a);
            PAIR2(rt_, nv2b, S2b, D2b);
        }

        float sl, sh, dl, dh;
        asm("mov.b64 {%0, %1}, %2;" : "=f"(sl), "=f"(sh) : "l"(S2a));
        asm("mov.b64 {%0, %1}, %2;" : "=f"(dl), "=f"(dh) : "l"(D2a));
        const float taua = (2 * jp + 0.5f) * (1.0f / QQ);
        s_part[u][2 * jp]     = fmaf(taua - 0.5f, dl + dh, 0.5f * (sl + sh));

        asm("mov.b64 {%0, %1}, %2;" : "=f"(sl), "=f"(sh) : "l"(S2b));
        asm("mov.b64 {%0, %1}, %2;" : "=f"(dl), "=f"(dh) : "l"(D2b));
        const float taub = (2 * jp + 1.5f) * (1.0f / QQ);
        s_part[u][2 * jp + 1] = fmaf(taub - 0.5f, dl + dh, 0.5f * (sl + sh));
    }
    __syncthreads();

    // ---- Deterministic fixed-order j-reduction ----
    if (tid < nu) {
        float s = 0.0f;
        #pragma unroll
        for (int j = 0; j < QQ; ++j) s += s_part[tid][j];
        out[(lo + tid) * BB + b] = s * (1.0f / QQ);
    }
}

extern "C" void kernel_launch(void* const* d_in, const int* in_sizes, int n_in,
                              void* d_out, int out_size)
{
    const float* reward    = (const float*)d_in[0];
    const int*   step_type = (const int*)  d_in[1];
    const float* discount  = (const float*)d_in[2];
    const float* value     = (const float*)d_in[3];
    const float* tvalue    = (const float*)d_in[4];
    float*       out       = (float*)d_out;

    dim3 gs(BQ / 2 / 128, NCH);                      // (100, 8)
    k_scan<<<gs, 128>>>(reward, step_type, discount, tvalue, out);

    dim3 gf(BB, 4);                                  // 2048 blocks, single wave
    k_fused<<<gf, NTHR>>>(reward, step_type, discount, value, tvalue, out);
}